// round 2
// baseline (speedup 1.0000x reference)
#include <cuda_runtime.h>
#include <math.h>

#define Bb 256
#define Tt 15
#define Ll 6
#define Uu 1000
#define Ee 1024
#define Vv 32000
#define G3 3000
#define LDXP 18000   // L * 3U

// ---------------- scratch (device globals; no allocation allowed) ----------
__device__ float g_Emb[Tt*Bb*Ee];        // [T*B, E]    embeddings, row m = t*B+b
__device__ float g_Wx[Ee*LDXP];          // [E, L*3U]   packed x-weights of all layers
__device__ float g_XP[Tt*Bb*LDXP];       // [T, B, L*3U] x-projections (+bias_in), later += skip
__device__ float g_MH[Ll*Bb*G3];         // [L, B, 3U]  recurrent projections (+bias_rec)
__device__ float g_H[Ll*Bb*Uu];          // [L, B, U]   hidden states
__device__ float g_final[Bb*Ll*Uu];      // [B, L*U]    repacked final states

// ---------------- small prep kernels ---------------------------------------
__global__ void embed_kernel(const int* __restrict__ tokens,
                             const float* __restrict__ table) {
    int m = blockIdx.x;              // m = t*B + b
    int t = m / Bb, b = m % Bb;
    int tok = tokens[b*Tt + t];
    const float4* src = (const float4*)(table + (size_t)tok * Ee);
    float4* dst = (float4*)(g_Emb + (size_t)m * Ee);
    dst[threadIdx.x] = src[threadIdx.x];   // 256 threads * float4 = 1024 floats
}

__global__ void packwx_kernel(const float* __restrict__ k0,
                              const float* __restrict__ krest) {
    int k = blockIdx.y;                                   // 0..1023
    int n = blockIdx.x * blockDim.x + threadIdx.x;        // 0..17999
    if (n >= LDXP) return;
    int l = n / G3, j = n % G3;
    float v = (l == 0) ? k0[(size_t)k * G3 + j]
                       : krest[(size_t)(l-1) * 2024 * G3 + (size_t)k * G3 + j];
    g_Wx[(size_t)k * LDXP + n] = v;
}

__global__ void copyh_kernel(const float* __restrict__ init) {
    int i = blockIdx.x * blockDim.x + threadIdx.x;
    if (i < Ll*Bb*Uu) g_H[i] = init[i];
}

// ---------------- generic fp32 GEMM: C[M,N] = A[M,K] * B[K,N] (+bias)(+=C) --
// BM=BN=64, BK=8, 256 threads, 4x4 micro-tile. M must be a multiple of 64.
__device__ __forceinline__ void gemm_body(
    const float* __restrict__ A, int lda,
    const float* __restrict__ Bm, int ldb,
    float* __restrict__ C, int ldc,
    const float* __restrict__ bias,
    int N, int K, bool accum)
{
    __shared__ float As[8][64];   // transposed: As[k][m]
    __shared__ float Bs[8][64];
    const int tid = threadIdx.x;
    const int m0 = blockIdx.y * 64;
    const int n0 = blockIdx.x * 64;
    const int tx = tid & 15, ty = tid >> 4;

    float acc[4][4];
#pragma unroll
    for (int i = 0; i < 4; i++)
#pragma unroll
        for (int j = 0; j < 4; j++) acc[i][j] = 0.f;

    const bool fullN = (n0 + 64 <= N);

    for (int k0 = 0; k0 < K; k0 += 8) {
        if (tid < 128) {                       // A tile: 64 rows x 8 k
            int row = tid >> 1;
            int kc  = (tid & 1) * 4;
            float4 v = *(const float4*)(A + (size_t)(m0 + row) * lda + k0 + kc);
            As[kc+0][row] = v.x; As[kc+1][row] = v.y;
            As[kc+2][row] = v.z; As[kc+3][row] = v.w;
        } else {                               // B tile: 8 k x 64 cols
            int t2 = tid - 128;
            int kr = t2 >> 4;
            int c4 = (t2 & 15) * 4;
            if (fullN) {
                *(float4*)&Bs[kr][c4] =
                    *(const float4*)(Bm + (size_t)(k0 + kr) * ldb + n0 + c4);
            } else {
#pragma unroll
                for (int q = 0; q < 4; q++) {
                    int n = n0 + c4 + q;
                    Bs[kr][c4+q] = (n < N) ? Bm[(size_t)(k0 + kr) * ldb + n] : 0.f;
                }
            }
        }
        __syncthreads();
#pragma unroll
        for (int kk = 0; kk < 8; kk++) {
            float4 av = *(const float4*)&As[kk][ty*4];
            float4 bv = *(const float4*)&Bs[kk][tx*4];
            float a[4] = {av.x, av.y, av.z, av.w};
            float b[4] = {bv.x, bv.y, bv.z, bv.w};
#pragma unroll
            for (int i = 0; i < 4; i++)
#pragma unroll
                for (int j = 0; j < 4; j++)
                    acc[i][j] = fmaf(a[i], b[j], acc[i][j]);
        }
        __syncthreads();
    }

#pragma unroll
    for (int i = 0; i < 4; i++) {
        int row = m0 + ty*4 + i;
#pragma unroll
        for (int j = 0; j < 4; j++) {
            int n = n0 + tx*4 + j;
            if (n < N) {
                float v = acc[i][j];
                if (bias)  v += bias[n];
                float* cp = C + (size_t)row * ldc + n;
                if (accum) v += *cp;
                *cp = v;
            }
        }
    }
}

__global__ void gemm_kernel(const float* A, int lda, const float* Bm, int ldb,
                            float* C, int ldc, const float* bias,
                            int N, int K, int accum) {
    gemm_body(A, lda, Bm, ldb, C, ldc, bias, N, K, accum != 0);
}

// Batched recurrent GEMM: all 6 layers in one launch (blockIdx.z = layer)
__global__ void gemm_rec_kernel(const float* __restrict__ R,
                                const float* __restrict__ br) {
    int l = blockIdx.z;
    gemm_body(g_H  + (size_t)l * Bb * Uu, Uu,
              R    + (size_t)l * Uu * G3, G3,
              g_MH + (size_t)l * Bb * G3, G3,
              br   + (size_t)l * G3,
              G3, Uu, false);
}

// ---------------- GRU gate pointwise (Keras reset_after=True, order z,r,h) --
__global__ void gate_kernel(int t, int l) {
    int idx = blockIdx.x * blockDim.x + threadIdx.x;
    if (idx >= Bb*Uu) return;
    int b = idx / Uu, j = idx % Uu;
    const float* xr = g_XP + (size_t)t * Bb * LDXP + (size_t)b * LDXP + l * G3;
    const float* hr = g_MH + (size_t)l * Bb * G3 + (size_t)b * G3;
    float xz = xr[j], xg = xr[j + Uu], xh = xr[j + 2*Uu];
    float hz = hr[j], hg = hr[j + Uu], hh = hr[j + 2*Uu];
    float z = 1.f / (1.f + __expf(-(xz + hz)));
    float r = 1.f / (1.f + __expf(-(xg + hg)));
    float cand = tanhf(xh + r * hh);
    float* hp = g_H + (size_t)l * Bb * Uu + idx;
    float ho = *hp;
    *hp = z * ho + (1.f - z) * cand;
}

__global__ void repack_kernel() {
    int idx = blockIdx.x * blockDim.x + threadIdx.x;
    if (idx >= Bb*Ll*Uu) return;
    int b = idx / (Ll*Uu);
    int rem = idx % (Ll*Uu);
    int l = rem / Uu, u = rem % Uu;
    g_final[idx] = g_H[((size_t)l * Bb + b) * Uu + u];
}

// ---------------- row softmax in-place on d_out [256, 32000] ---------------
__global__ void softmax_kernel(float* __restrict__ out) {
    int row = blockIdx.x;
    float* p = out + (size_t)row * Vv;
    __shared__ float red[256];
    int tid = threadIdx.x;

    float m = -1e30f;
    for (int i = tid; i < Vv; i += 256) m = fmaxf(m, p[i]);
    red[tid] = m; __syncthreads();
    for (int s = 128; s > 0; s >>= 1) {
        if (tid < s) red[tid] = fmaxf(red[tid], red[tid + s]);
        __syncthreads();
    }
    m = red[0]; __syncthreads();

    float sum = 0.f;
    for (int i = tid; i < Vv; i += 256) {
        float e = expf(p[i] - m);
        p[i] = e;
        sum += e;
    }
    red[tid] = sum; __syncthreads();
    for (int s = 128; s > 0; s >>= 1) {
        if (tid < s) red[tid] += red[tid + s];
        __syncthreads();
    }
    float inv = 1.f / red[0];
    for (int i = tid; i < Vv; i += 256) p[i] *= inv;
}

// ---------------- launch ---------------------------------------------------
extern "C" void kernel_launch(void* const* d_in, const int* in_sizes, int n_in,
                              void* d_out, int out_size) {
    const int*   tokens       = (const int*)  d_in[0];
    const float* init_states  = (const float*)d_in[1];
    const float* emb_table    = (const float*)d_in[2];
    const float* kernel0      = (const float*)d_in[3];
    const float* kernels_rest = (const float*)d_in[4];
    const float* rec_kernels  = (const float*)d_in[5];
    const float* bias_in      = (const float*)d_in[6];
    const float* bias_rec     = (const float*)d_in[7];
    const float* dense_kernel = (const float*)d_in[8];
    const float* dense_bias   = (const float*)d_in[9];
    float* out = (float*)d_out;

    float *pEmb, *pWx, *pXP, *pH, *pFinal;
    cudaGetSymbolAddress((void**)&pEmb,   g_Emb);
    cudaGetSymbolAddress((void**)&pWx,    g_Wx);
    cudaGetSymbolAddress((void**)&pXP,    g_XP);
    cudaGetSymbolAddress((void**)&pH,     g_H);
    cudaGetSymbolAddress((void**)&pFinal, g_final);

    // 1. prep
    embed_kernel<<<Tt*Bb, Ee/4>>>(tokens, emb_table);
    packwx_kernel<<<dim3((LDXP+255)/256, Ee), 256>>>(kernel0, kernels_rest);
    copyh_kernel<<<(Ll*Bb*Uu + 255)/256, 256>>>(init_states);

    // 2. all x-projections for all timesteps & layers in one GEMM (+bias_in)
    gemm_kernel<<<dim3((LDXP+63)/64, (Tt*Bb)/64), 256>>>(
        pEmb, Ee, pWx, LDXP, pXP, LDXP, bias_in, LDXP, Ee, 0);

    // 3. sequential recurrence
    for (int t = 0; t < Tt; t++) {
        gemm_rec_kernel<<<dim3((G3+63)/64, Bb/64, Ll), 256>>>(rec_kernels, bias_rec);
        for (int l = 0; l < Ll; l++) {
            if (l > 0) {
                // XP[t, :, l*3U:..] += H[l-1] @ kernels_rest[l-1][E:, :]
                gemm_kernel<<<dim3((G3+63)/64, Bb/64), 256>>>(
                    pH + (size_t)(l-1) * Bb * Uu, Uu,
                    kernels_rest + (size_t)(l-1) * 2024 * G3 + (size_t)Ee * G3, G3,
                    pXP + (size_t)t * Bb * LDXP + l * G3, LDXP,
                    nullptr, G3, Uu, 1);
            }
            gate_kernel<<<(Bb*Uu + 255)/256, 256>>>(t, l);
        }
    }

    // 4. head
    repack_kernel<<<(Bb*Ll*Uu + 255)/256, 256>>>();
    gemm_kernel<<<dim3(Vv/64, Bb/64), 256>>>(
        pFinal, Ll*Uu, dense_kernel, Vv, out, Vv, dense_bias, Vv, Ll*Uu, 0);
    softmax_kernel<<<Bb, 256>>>(out);
}

// round 3
// speedup vs baseline: 1.3323x; 1.3323x over previous
#include <cuda_runtime.h>
#include <math.h>

#define Bb 256
#define Tt 15
#define Ll 6
#define Uu 1000
#define Ee 1024
#define Vv 32000
#define G3 3000
#define LDXP 18000   // L * 3U

// ---------------- scratch (device globals; no allocation allowed) ----------
__device__ float g_Emb[Tt*Bb*Ee];        // [T*B, E]
__device__ float g_Wx[Ee*LDXP];          // [E, L*3U]
__device__ float g_XP[Tt*Bb*LDXP];       // [T, B, L*3U]
__device__ float g_MH[Ll*Bb*G3];         // [L, B, 3U]
__device__ float g_H[Ll*Bb*Uu];          // [L, B, U]
__device__ float g_final[Bb*Ll*Uu];      // [B, L*U]

// ---------------- helpers ---------------------------------------------------
__device__ __forceinline__ unsigned f2tf(float x) {
    unsigned r;
    asm("cvt.rna.tf32.f32 %0, %1;\n" : "=r"(r) : "f"(x));
    return r;
}

__device__ __forceinline__ void mma_tf32(float c[4], const unsigned a[4], const unsigned b[2]) {
    asm volatile(
        "mma.sync.aligned.m16n8k8.row.col.f32.tf32.tf32.f32 "
        "{%0,%1,%2,%3}, {%4,%5,%6,%7}, {%8,%9}, {%0,%1,%2,%3};\n"
        : "+f"(c[0]), "+f"(c[1]), "+f"(c[2]), "+f"(c[3])
        : "r"(a[0]), "r"(a[1]), "r"(a[2]), "r"(a[3]), "r"(b[0]), "r"(b[1]));
}

// ---------------- small prep kernels ---------------------------------------
__global__ void embed_kernel(const int* __restrict__ tokens,
                             const float* __restrict__ table) {
    int m = blockIdx.x;              // m = t*B + b
    int t = m / Bb, b = m % Bb;
    int tok = tokens[b*Tt + t];
    const float4* src = (const float4*)(table + (size_t)tok * Ee);
    float4* dst = (float4*)(g_Emb + (size_t)m * Ee);
    dst[threadIdx.x] = src[threadIdx.x];
}

__global__ void packwx_kernel(const float* __restrict__ k0,
                              const float* __restrict__ krest) {
    int k = blockIdx.y;
    int n = blockIdx.x * blockDim.x + threadIdx.x;
    if (n >= LDXP) return;
    int l = n / G3, j = n % G3;
    float v = (l == 0) ? k0[(size_t)k * G3 + j]
                       : krest[(size_t)(l-1) * 2024 * G3 + (size_t)k * G3 + j];
    g_Wx[(size_t)k * LDXP + n] = v;
}

__global__ void copyh_kernel(const float* __restrict__ init) {
    int i = blockIdx.x * blockDim.x + threadIdx.x;
    if (i < Ll*Bb*Uu) g_H[i] = init[i];
}

// ---------------- TF32 tensor-core GEMM -------------------------------------
// C[M,N] = A[M,K] * B[K,N] (+bias)(+=C)
// BM=128, BN=128, BK=16. 256 threads = 8 warps (2 M x 4 N), warp tile 64x32.
// M must be a multiple of 128. N, K arbitrary.
__device__ __forceinline__ void gemm_tc_body(
    const float* __restrict__ A, int lda,
    const float* __restrict__ Bm, int ldb,
    float* __restrict__ C, int ldc,
    const float* __restrict__ bias,
    int N, int K, bool accum)
{
    __shared__ unsigned As[16][136];   // k-major, +8 pad -> conflict free
    __shared__ unsigned Bs[16][136];

    const int tid  = threadIdx.x;
    const int m0   = blockIdx.y * 128;
    const int n0   = blockIdx.x * 128;
    const int warp = tid >> 5, lane = tid & 31;
    const int gid  = lane >> 2, tig = lane & 3;
    const int wM   = (warp >> 2) * 64;   // 0 or 64
    const int wN   = (warp & 3)  * 32;   // 0,32,64,96

    float acc[4][4][4];
#pragma unroll
    for (int i = 0; i < 4; i++)
#pragma unroll
        for (int j = 0; j < 4; j++)
#pragma unroll
            for (int q = 0; q < 4; q++) acc[i][j][q] = 0.f;

    for (int k0 = 0; k0 < K; k0 += 16) {
        // ---- stage A tile (128 x 16), transpose to k-major, cvt to tf32 ----
#pragma unroll
        for (int h = 0; h < 2; h++) {
            int idx = tid + h * 256;
            int m   = idx >> 2;
            int kq  = (idx & 3) * 4;
            const float* src = A + (size_t)(m0 + m) * lda + k0 + kq;
            float4 v;
            if (k0 + kq + 4 <= K) {
                v = *(const float4*)src;
            } else {
                v.x = (k0 + kq + 0 < K) ? src[0] : 0.f;
                v.y = (k0 + kq + 1 < K) ? src[1] : 0.f;
                v.z = (k0 + kq + 2 < K) ? src[2] : 0.f;
                v.w = (k0 + kq + 3 < K) ? src[3] : 0.f;
            }
            As[kq+0][m] = f2tf(v.x);
            As[kq+1][m] = f2tf(v.y);
            As[kq+2][m] = f2tf(v.z);
            As[kq+3][m] = f2tf(v.w);
        }
        // ---- stage B tile (16 x 128), cvt to tf32 ----
#pragma unroll
        for (int h = 0; h < 2; h++) {
            int idx = tid + h * 256;
            int kr  = idx >> 5;
            int c4  = (idx & 31) * 4;
            float4 v = make_float4(0.f, 0.f, 0.f, 0.f);
            if (k0 + kr < K) {
                const float* src = Bm + (size_t)(k0 + kr) * ldb + n0 + c4;
                if (n0 + c4 + 4 <= N) {
                    v = *(const float4*)src;
                } else {
                    if (n0 + c4 + 0 < N) v.x = src[0];
                    if (n0 + c4 + 1 < N) v.y = src[1];
                    if (n0 + c4 + 2 < N) v.z = src[2];
                    if (n0 + c4 + 3 < N) v.w = src[3];
                }
            }
            uint4 u = make_uint4(f2tf(v.x), f2tf(v.y), f2tf(v.z), f2tf(v.w));
            *(uint4*)&Bs[kr][c4] = u;
        }
        __syncthreads();

        // ---- compute: 2 k8 steps, 4x4 mma tiles per warp ----
#pragma unroll
        for (int ks = 0; ks < 16; ks += 8) {
            unsigned a[4][4], b[4][2];
#pragma unroll
            for (int i = 0; i < 4; i++) {
                int mB = wM + i * 16 + gid;
                a[i][0] = As[ks + tig    ][mB];
                a[i][1] = As[ks + tig    ][mB + 8];
                a[i][2] = As[ks + tig + 4][mB];
                a[i][3] = As[ks + tig + 4][mB + 8];
            }
#pragma unroll
            for (int j = 0; j < 4; j++) {
                int nB = wN + j * 8 + gid;
                b[j][0] = Bs[ks + tig    ][nB];
                b[j][1] = Bs[ks + tig + 4][nB];
            }
#pragma unroll
            for (int i = 0; i < 4; i++)
#pragma unroll
                for (int j = 0; j < 4; j++)
                    mma_tf32(acc[i][j], a[i], b[j]);
        }
        __syncthreads();
    }

    // ---- epilogue ----
#pragma unroll
    for (int i = 0; i < 4; i++) {
        int r0 = m0 + wM + i * 16 + gid;
        int r1 = r0 + 8;
#pragma unroll
        for (int j = 0; j < 4; j++) {
            int c = n0 + wN + j * 8 + 2 * tig;   // even
            if (c + 2 <= N) {
                float b0 = bias ? bias[c] : 0.f;
                float b1 = bias ? bias[c+1] : 0.f;
                float2* p0 = (float2*)(C + (size_t)r0 * ldc + c);
                float2* p1 = (float2*)(C + (size_t)r1 * ldc + c);
                float2 v0 = make_float2(acc[i][j][0] + b0, acc[i][j][1] + b1);
                float2 v1 = make_float2(acc[i][j][2] + b0, acc[i][j][3] + b1);
                if (accum) {
                    float2 o0 = *p0, o1 = *p1;
                    v0.x += o0.x; v0.y += o0.y;
                    v1.x += o1.x; v1.y += o1.y;
                }
                *p0 = v0; *p1 = v1;
            } else {
#pragma unroll
                for (int q = 0; q < 2; q++) {
                    int cc = c + q;
                    if (cc < N) {
                        float bq = bias ? bias[cc] : 0.f;
                        float* q0 = C + (size_t)r0 * ldc + cc;
                        float* q1 = C + (size_t)r1 * ldc + cc;
                        float v0 = acc[i][j][q] + bq;
                        float v1 = acc[i][j][2+q] + bq;
                        if (accum) { v0 += *q0; v1 += *q1; }
                        *q0 = v0; *q1 = v1;
                    }
                }
            }
        }
    }
}

__global__ void __launch_bounds__(256)
gemm_tc_kernel(const float* A, int lda, const float* Bm, int ldb,
               float* C, int ldc, const float* bias,
               int N, int K, int accum) {
    gemm_tc_body(A, lda, Bm, ldb, C, ldc, bias, N, K, accum != 0);
}

// Batched recurrent GEMM: all 6 layers in one launch (blockIdx.z = layer)
__global__ void __launch_bounds__(256)
gemm_rec_kernel(const float* __restrict__ R, const float* __restrict__ br) {
    int l = blockIdx.z;
    gemm_tc_body(g_H  + (size_t)l * Bb * Uu, Uu,
                 R    + (size_t)l * Uu * G3, G3,
                 g_MH + (size_t)l * Bb * G3, G3,
                 br   + (size_t)l * G3,
                 G3, Uu, false);
}

// ---------------- GRU gate pointwise (Keras reset_after=True, order z,r,h) --
__global__ void gate_kernel(int t, int l) {
    int idx = blockIdx.x * blockDim.x + threadIdx.x;
    if (idx >= Bb*Uu) return;
    int b = idx / Uu, j = idx % Uu;
    const float* xr = g_XP + (size_t)t * Bb * LDXP + (size_t)b * LDXP + l * G3;
    const float* hr = g_MH + (size_t)l * Bb * G3 + (size_t)b * G3;
    float xz = xr[j], xg = xr[j + Uu], xh = xr[j + 2*Uu];
    float hz = hr[j], hg = hr[j + Uu], hh = hr[j + 2*Uu];
    float z = 1.f / (1.f + __expf(-(xz + hz)));
    float r = 1.f / (1.f + __expf(-(xg + hg)));
    float cand = tanhf(xh + r * hh);
    float* hp = g_H + (size_t)l * Bb * Uu + idx;
    float ho = *hp;
    *hp = z * ho + (1.f - z) * cand;
}

__global__ void repack_kernel() {
    int idx = blockIdx.x * blockDim.x + threadIdx.x;
    if (idx >= Bb*Ll*Uu) return;
    int b = idx / (Ll*Uu);
    int rem = idx % (Ll*Uu);
    int l = rem / Uu, u = rem % Uu;
    g_final[idx] = g_H[((size_t)l * Bb + b) * Uu + u];
}

// ---------------- row softmax in-place on d_out [256, 32000] ---------------
__global__ void softmax_kernel(float* __restrict__ out) {
    int row = blockIdx.x;
    float* p = out + (size_t)row * Vv;
    __shared__ float red[256];
    int tid = threadIdx.x;

    float m = -1e30f;
    for (int i = tid; i < Vv; i += 256) m = fmaxf(m, p[i]);
    red[tid] = m; __syncthreads();
    for (int s = 128; s > 0; s >>= 1) {
        if (tid < s) red[tid] = fmaxf(red[tid], red[tid + s]);
        __syncthreads();
    }
    m = red[0]; __syncthreads();

    float sum = 0.f;
    for (int i = tid; i < Vv; i += 256) {
        float e = expf(p[i] - m);
        p[i] = e;
        sum += e;
    }
    red[tid] = sum; __syncthreads();
    for (int s = 128; s > 0; s >>= 1) {
        if (tid < s) red[tid] += red[tid + s];
        __syncthreads();
    }
    float inv = 1.f / red[0];
    for (int i = tid; i < Vv; i += 256) p[i] *= inv;
}

// ---------------- launch ---------------------------------------------------
extern "C" void kernel_launch(void* const* d_in, const int* in_sizes, int n_in,
                              void* d_out, int out_size) {
    const int*   tokens       = (const int*)  d_in[0];
    const float* init_states  = (const float*)d_in[1];
    const float* emb_table    = (const float*)d_in[2];
    const float* kernel0      = (const float*)d_in[3];
    const float* kernels_rest = (const float*)d_in[4];
    const float* rec_kernels  = (const float*)d_in[5];
    const float* bias_in      = (const float*)d_in[6];
    const float* bias_rec     = (const float*)d_in[7];
    const float* dense_kernel = (const float*)d_in[8];
    const float* dense_bias   = (const float*)d_in[9];
    float* out = (float*)d_out;

    float *pEmb, *pWx, *pXP, *pH, *pFinal;
    cudaGetSymbolAddress((void**)&pEmb,   g_Emb);
    cudaGetSymbolAddress((void**)&pWx,    g_Wx);
    cudaGetSymbolAddress((void**)&pXP,    g_XP);
    cudaGetSymbolAddress((void**)&pH,     g_H);
    cudaGetSymbolAddress((void**)&pFinal, g_final);

    // 1. prep
    embed_kernel<<<Tt*Bb, Ee/4>>>(tokens, emb_table);
    packwx_kernel<<<dim3((LDXP+255)/256, Ee), 256>>>(kernel0, kernels_rest);
    copyh_kernel<<<(Ll*Bb*Uu + 255)/256, 256>>>(init_states);

    // 2. all x-projections for all timesteps & layers in one GEMM (+bias_in)
    gemm_tc_kernel<<<dim3((LDXP+127)/128, (Tt*Bb)/128), 256>>>(
        pEmb, Ee, pWx, LDXP, pXP, LDXP, bias_in, LDXP, Ee, 0);

    // 3. sequential recurrence
    for (int t = 0; t < Tt; t++) {
        gemm_rec_kernel<<<dim3((G3+127)/128, Bb/128, Ll), 256>>>(rec_kernels, bias_rec);
        for (int l = 0; l < Ll; l++) {
            if (l > 0) {
                // XP[t, :, l*3U:..] += H[l-1] @ kernels_rest[l-1][E:, :]
                gemm_tc_kernel<<<dim3((G3+127)/128, Bb/128), 256>>>(
                    pH + (size_t)(l-1) * Bb * Uu, Uu,
                    kernels_rest + (size_t)(l-1) * 2024 * G3 + (size_t)Ee * G3, G3,
                    pXP + (size_t)t * Bb * LDXP + l * G3, LDXP,
                    nullptr, G3, Uu, 1);
            }
            gate_kernel<<<(Bb*Uu + 255)/256, 256>>>(t, l);
        }
    }

    // 4. head
    repack_kernel<<<(Bb*Ll*Uu + 255)/256, 256>>>();
    gemm_tc_kernel<<<dim3(Vv/128, Bb/128), 256>>>(
        pFinal, Ll*Uu, dense_kernel, Vv, out, Vv, dense_bias, Vv, Ll*Uu, 0);
    softmax_kernel<<<Bb, 256>>>(out);
}

// round 4
// speedup vs baseline: 5.6396x; 4.2331x over previous
#include <cuda_runtime.h>
#include <cuda_bf16.h>
#include <math.h>

#define Bb 256
#define Tt 15
#define Ll 6
#define Uu 1000
#define Ee 1024
#define Vv 32000
#define G3 3000
#define LDXP 18000   // L * 3U
#define EU 2024      // E + U (rows of kernels_rest)
#define KP_E 512     // E/2 pairs
#define KP_U 500     // U/2 pairs
#define KP_D 3000    // (L*U)/2 pairs

// ---------------- scratch (device globals; no allocation allowed) ----------
__device__ __align__(16) unsigned g_Embp[Tt*Bb*KP_E];      // [T*B][512]  bf16-pair emb
__device__ __align__(16) unsigned g_Wxp[KP_E*LDXP];        // [512][18000]
__device__ __align__(16) unsigned g_Rp[Ll*KP_U*G3];        // [l][500][3000]
__device__ __align__(16) unsigned g_Sp[(Ll-1)*KP_U*G3];    // [l-1][500][3000]
__device__ __align__(16) unsigned g_Dp[(size_t)KP_D*Vv];   // [3000][32000]
__device__ __align__(16) unsigned g_Hp[Bb*Ll*KP_U];        // [b][l*500+jj]
__device__ __align__(16) float    g_XP[(size_t)Tt*Bb*LDXP];
__device__ __align__(16) float    g_MH[(size_t)Ll*Bb*G3];
__device__ __align__(16) float    g_H[Ll*Bb*Uu];

// ---------------- helpers ---------------------------------------------------
__device__ __forceinline__ unsigned packbf(float a, float b) {
    __nv_bfloat162 h = __floats2bfloat162_rn(a, b);   // x=a (lo), y=b (hi)
    return *reinterpret_cast<unsigned*>(&h);
}

__device__ __forceinline__ void mma_bf16(float c[4], const unsigned a[4], const unsigned b[2]) {
    asm volatile(
        "mma.sync.aligned.m16n8k16.row.col.f32.bf16.bf16.f32 "
        "{%0,%1,%2,%3}, {%4,%5,%6,%7}, {%8,%9}, {%0,%1,%2,%3};\n"
        : "+f"(c[0]), "+f"(c[1]), "+f"(c[2]), "+f"(c[3])
        : "r"(a[0]), "r"(a[1]), "r"(a[2]), "r"(a[3]), "r"(b[0]), "r"(b[1]));
}

__device__ __forceinline__ void cp16(void* dst, const void* src, bool valid) {
    unsigned s = (unsigned)__cvta_generic_to_shared(dst);
    asm volatile("cp.async.cg.shared.global [%0], [%1], 16, %2;\n"
                 :: "r"(s), "l"(src), "r"(valid ? 16 : 0));
}
#define CP_COMMIT() asm volatile("cp.async.commit_group;\n")
#define CP_WAIT1()  asm volatile("cp.async.wait_group 1;\n")
#define CP_WAIT0()  asm volatile("cp.async.wait_group 0;\n")

// ---------------- bf16 tensor-core GEMM, cp.async double-buffered -----------
// C[M,N] = A[M,K] * B[K,N] (+bias)(+=C). A,B pre-packed bf16 k-pairs (uint32).
// ldap/ldbp in pairs. M multiple of BM. KP = K/2 (multiple of 4).
template<int BM, int BN, int WM, int WN>
__device__ __forceinline__ void gemm_bf16_body(
    const unsigned* __restrict__ Ap, int ldap,
    const unsigned* __restrict__ Bp, int ldbp,
    float* __restrict__ C, int ldc,
    const float* __restrict__ bias,
    int N, int KP, bool accum)
{
    constexpr int NTH = WM * WN * 32;
    constexpr int KPP = 20;        // A smem row stride (words): conflict-free
    constexpr int BNP = BN + 8;    // B smem row stride
    constexpr int MT  = BM / WM / 16;
    constexpr int NT  = BN / WN / 8;
    constexpr int ACH = (BM * 4) / NTH;       // A 16B-chunks per thread
    constexpr int BCH = (16 * BN / 4) / NTH;  // B 16B-chunks per thread
    constexpr int BN4 = BN / 4;

    __shared__ alignas(16) unsigned As[2][BM][KPP];
    __shared__ alignas(16) unsigned Bs[2][16][BNP];

    const int tid  = threadIdx.x;
    const int m0   = blockIdx.y * BM;
    const int n0   = blockIdx.x * BN;
    const int warp = tid >> 5, lane = tid & 31;
    const int gid  = lane >> 2, tig = lane & 3;
    const int wM   = (warp / WN) * (BM / WM);
    const int wN   = (warp % WN) * (BN / WN);

    float acc[MT][NT][4];
#pragma unroll
    for (int i = 0; i < MT; i++)
#pragma unroll
        for (int j = 0; j < NT; j++)
#pragma unroll
            for (int q = 0; q < 4; q++) acc[i][j][q] = 0.f;

    const int NC = (KP + 15) >> 4;

    auto issue = [&](int s) {
        const int kp0 = s * 16;
        const int buf = s & 1;
#pragma unroll
        for (int h = 0; h < ACH; h++) {
            int c = tid + h * NTH;
            int row = c >> 2, q = c & 3;
            bool v = (kp0 + q * 4) < KP;
            const unsigned* src = Ap + (size_t)(m0 + row) * ldap + (v ? (kp0 + q * 4) : 0);
            cp16(&As[buf][row][q * 4], src, v);
        }
#pragma unroll
        for (int h = 0; h < BCH; h++) {
            int c = tid + h * NTH;
            int kr = c / BN4, qn = c % BN4;
            bool v = ((kp0 + kr) < KP) && ((n0 + qn * 4) < N);
            const unsigned* src = Bp + (size_t)(v ? (kp0 + kr) : 0) * ldbp + (v ? (n0 + qn * 4) : 0);
            cp16(&Bs[buf][kr][qn * 4], src, v);
        }
        CP_COMMIT();
    };

    issue(0);
    for (int s = 0; s < NC; s++) {
        if (s + 1 < NC) { issue(s + 1); CP_WAIT1(); }
        else            { CP_WAIT0(); }
        __syncthreads();
        const int buf = s & 1;
#pragma unroll
        for (int ks = 0; ks < 2; ks++) {
            unsigned af[MT][4], bfr[NT][2];
#pragma unroll
            for (int i = 0; i < MT; i++) {
                int r = wM + i * 16 + gid;
                af[i][0] = As[buf][r    ][ks * 8 + tig];
                af[i][1] = As[buf][r + 8][ks * 8 + tig];
                af[i][2] = As[buf][r    ][ks * 8 + 4 + tig];
                af[i][3] = As[buf][r + 8][ks * 8 + 4 + tig];
            }
#pragma unroll
            for (int j = 0; j < NT; j++) {
                int cn = wN + j * 8 + gid;
                bfr[j][0] = Bs[buf][ks * 8 + tig    ][cn];
                bfr[j][1] = Bs[buf][ks * 8 + 4 + tig][cn];
            }
#pragma unroll
            for (int i = 0; i < MT; i++)
#pragma unroll
                for (int j = 0; j < NT; j++)
                    mma_bf16(acc[i][j], af[i], bfr[j]);
        }
        __syncthreads();
    }

    // ---- epilogue ----
#pragma unroll
    for (int i = 0; i < MT; i++) {
        int r0 = m0 + wM + i * 16 + gid;
        int r1 = r0 + 8;
#pragma unroll
        for (int j = 0; j < NT; j++) {
            int c = n0 + wN + j * 8 + 2 * tig;
            if (c < N) {
                float b0 = bias ? bias[c]     : 0.f;
                float b1 = bias ? bias[c + 1] : 0.f;
                float2* p0 = (float2*)(C + (size_t)r0 * ldc + c);
                float2* p1 = (float2*)(C + (size_t)r1 * ldc + c);
                float2 v0 = make_float2(acc[i][j][0] + b0, acc[i][j][1] + b1);
                float2 v1 = make_float2(acc[i][j][2] + b0, acc[i][j][3] + b1);
                if (accum) {
                    float2 o0 = *p0, o1 = *p1;
                    v0.x += o0.x; v0.y += o0.y;
                    v1.x += o1.x; v1.y += o1.y;
                }
                *p0 = v0; *p1 = v1;
            }
        }
    }
}

template<int BM, int BN, int WM, int WN>
__global__ void __launch_bounds__(WM*WN*32)
gemm_bf16_kernel(const unsigned* Ap, int ldap, const unsigned* Bp, int ldbp,
                 float* C, int ldc, const float* bias, int N, int KP, int accum) {
    gemm_bf16_body<BM, BN, WM, WN>(Ap, ldap, Bp, ldbp, C, ldc, bias, N, KP, accum != 0);
}

// Batched recurrent GEMM: blockIdx.z = layer
__global__ void __launch_bounds__(128)
gemm_rec_kernel(const unsigned* __restrict__ Hp, const unsigned* __restrict__ Rp,
                float* __restrict__ MH, const float* __restrict__ br) {
    int l = blockIdx.z;
    gemm_bf16_body<64, 64, 2, 2>(
        Hp + l * KP_U, Ll * KP_U,
        Rp + (size_t)l * KP_U * G3, G3,
        MH + (size_t)l * Bb * G3, G3,
        br + l * G3, G3, KP_U, false);
}

// ---------------- prep / pack kernels ---------------------------------------
__global__ void embed_kernel(const int* __restrict__ tokens,
                             const float* __restrict__ table) {
    int m = blockIdx.x;              // m = t*B + b
    int t = m / Bb, b = m % Bb;
    int tok = tokens[b * Tt + t];
    float4 v = ((const float4*)(table + (size_t)tok * Ee))[threadIdx.x];  // 256 thr
    g_Embp[(size_t)m * KP_E + threadIdx.x * 2]     = packbf(v.x, v.y);
    g_Embp[(size_t)m * KP_E + threadIdx.x * 2 + 1] = packbf(v.z, v.w);
}

__global__ void packwx_kernel(const float* __restrict__ k0,
                              const float* __restrict__ krest) {
    int n = blockIdx.x * 256 + threadIdx.x;
    int kp = blockIdx.y;                   // 0..511
    if (n >= LDXP) return;
    int l = n / G3, j = n % G3;
    int k = 2 * kp;
    float a, b;
    if (l == 0) {
        a = k0[(size_t)k * G3 + j];
        b = k0[(size_t)(k + 1) * G3 + j];
    } else {
        const float* base = krest + (size_t)(l - 1) * EU * G3;
        a = base[(size_t)k * G3 + j];
        b = base[(size_t)(k + 1) * G3 + j];
    }
    g_Wxp[(size_t)kp * LDXP + n] = packbf(a, b);
}

__global__ void packrec_kernel(const float* __restrict__ rec) {
    int n = blockIdx.x * 256 + threadIdx.x;
    int kp = blockIdx.y, l = blockIdx.z;
    if (n >= G3) return;
    const float* src = rec + (size_t)l * Uu * G3;
    g_Rp[((size_t)l * KP_U + kp) * G3 + n] =
        packbf(src[(size_t)(2 * kp) * G3 + n], src[(size_t)(2 * kp + 1) * G3 + n]);
}

__global__ void packskip_kernel(const float* __restrict__ krest) {
    int n = blockIdx.x * 256 + threadIdx.x;
    int kp = blockIdx.y, l = blockIdx.z;   // l = 0..4
    if (n >= G3) return;
    const float* src = krest + (size_t)l * EU * G3 + (size_t)Ee * G3;
    g_Sp[((size_t)l * KP_U + kp) * G3 + n] =
        packbf(src[(size_t)(2 * kp) * G3 + n], src[(size_t)(2 * kp + 1) * G3 + n]);
}

__global__ void packdense_kernel(const float* __restrict__ dk) {
    int n = blockIdx.x * 256 + threadIdx.x;   // 0..31999
    int kp = blockIdx.y;                      // 0..2999
    g_Dp[(size_t)kp * Vv + n] =
        packbf(dk[(size_t)(2 * kp) * Vv + n], dk[(size_t)(2 * kp + 1) * Vv + n]);
}

__global__ void copyh_kernel(const float* __restrict__ init) {
    int i = blockIdx.x * 256 + threadIdx.x;
    if (i < Ll * Bb * Uu) g_H[i] = init[i];
}

__global__ void packh_kernel(const float* __restrict__ init) {
    int idx = blockIdx.x * 256 + threadIdx.x;   // over L*B*500
    if (idx >= Ll * Bb * KP_U) return;
    int l = idx / (Bb * KP_U);
    int r = idx % (Bb * KP_U);
    int b = r / KP_U, jj = r % KP_U;
    const float* src = init + ((size_t)l * Bb + b) * Uu + 2 * jj;
    g_Hp[(size_t)b * (Ll * KP_U) + l * KP_U + jj] = packbf(src[0], src[1]);
}

// ---------------- GRU gate pointwise (Keras reset_after=True, order z,r,h) --
__global__ void gate_kernel(int t, int l) {
    int idx = blockIdx.x * 256 + threadIdx.x;
    if (idx >= Bb * KP_U) return;
    int b = idx / KP_U, jj = idx % KP_U;
    int j = 2 * jj;
    const float* xr = g_XP + ((size_t)t * Bb + b) * LDXP + l * G3;
    const float* hr = g_MH + ((size_t)l * Bb + b) * G3;
    float* hp = g_H + ((size_t)l * Bb + b) * Uu;
    float hn[2];
#pragma unroll
    for (int q = 0; q < 2; q++) {
        float xz = xr[j + q], xg = xr[j + q + Uu], xh = xr[j + q + 2 * Uu];
        float hz = hr[j + q], hg = hr[j + q + Uu], hh = hr[j + q + 2 * Uu];
        float z = 1.f / (1.f + __expf(-(xz + hz)));
        float r = 1.f / (1.f + __expf(-(xg + hg)));
        float cand = tanhf(xh + r * hh);
        float ho = hp[j + q];
        hn[q] = z * ho + (1.f - z) * cand;
        hp[j + q] = hn[q];
    }
    g_Hp[(size_t)b * (Ll * KP_U) + l * KP_U + jj] = packbf(hn[0], hn[1]);
}

// ---------------- row softmax in-place on d_out [256, 32000] ---------------
__global__ void softmax_kernel(float* __restrict__ out) {
    int row = blockIdx.x;
    float* p = out + (size_t)row * Vv;
    __shared__ float red[256];
    int tid = threadIdx.x;

    float m = -1e30f;
    for (int i = tid; i < Vv; i += 256) m = fmaxf(m, p[i]);
    red[tid] = m; __syncthreads();
    for (int s = 128; s > 0; s >>= 1) {
        if (tid < s) red[tid] = fmaxf(red[tid], red[tid + s]);
        __syncthreads();
    }
    m = red[0]; __syncthreads();

    float sum = 0.f;
    for (int i = tid; i < Vv; i += 256) {
        float e = expf(p[i] - m);
        p[i] = e;
        sum += e;
    }
    red[tid] = sum; __syncthreads();
    for (int s = 128; s > 0; s >>= 1) {
        if (tid < s) red[tid] += red[tid + s];
        __syncthreads();
    }
    float inv = 1.f / red[0];
    for (int i = tid; i < Vv; i += 256) p[i] *= inv;
}

// ---------------- launch ---------------------------------------------------
extern "C" void kernel_launch(void* const* d_in, const int* in_sizes, int n_in,
                              void* d_out, int out_size) {
    const int*   tokens       = (const int*)  d_in[0];
    const float* init_states  = (const float*)d_in[1];
    const float* emb_table    = (const float*)d_in[2];
    const float* kernel0      = (const float*)d_in[3];
    const float* kernels_rest = (const float*)d_in[4];
    const float* rec_kernels  = (const float*)d_in[5];
    const float* bias_in      = (const float*)d_in[6];
    const float* bias_rec     = (const float*)d_in[7];
    const float* dense_kernel = (const float*)d_in[8];
    const float* dense_bias   = (const float*)d_in[9];
    float* out = (float*)d_out;

    unsigned *pEmbp, *pWxp, *pRp, *pSp, *pDp, *pHp;
    float *pXP, *pMH;
    cudaGetSymbolAddress((void**)&pEmbp, g_Embp);
    cudaGetSymbolAddress((void**)&pWxp,  g_Wxp);
    cudaGetSymbolAddress((void**)&pRp,   g_Rp);
    cudaGetSymbolAddress((void**)&pSp,   g_Sp);
    cudaGetSymbolAddress((void**)&pDp,   g_Dp);
    cudaGetSymbolAddress((void**)&pHp,   g_Hp);
    cudaGetSymbolAddress((void**)&pXP,   g_XP);
    cudaGetSymbolAddress((void**)&pMH,   g_MH);

    // 1. prep: embed + pack all weights to bf16 pairs + init hidden state
    embed_kernel<<<Tt*Bb, 256>>>(tokens, emb_table);
    packwx_kernel<<<dim3((LDXP+255)/256, KP_E), 256>>>(kernel0, kernels_rest);
    packrec_kernel<<<dim3((G3+255)/256, KP_U, Ll), 256>>>(rec_kernels);
    packskip_kernel<<<dim3((G3+255)/256, KP_U, Ll-1), 256>>>(kernels_rest);
    packdense_kernel<<<dim3(Vv/256, KP_D), 256>>>(dense_kernel);
    copyh_kernel<<<(Ll*Bb*Uu + 255)/256, 256>>>(init_states);
    packh_kernel<<<(Ll*Bb*KP_U + 255)/256, 256>>>(init_states);

    // 2. all x-projections for all timesteps & layers in one GEMM (+bias_in)
    gemm_bf16_kernel<128,128,2,4><<<dim3((LDXP+127)/128, (Tt*Bb)/128), 256>>>(
        pEmbp, KP_E, pWxp, LDXP, pXP, LDXP, bias_in, LDXP, KP_E, 0);

    // 3. sequential recurrence
    for (int t = 0; t < Tt; t++) {
        gemm_rec_kernel<<<dim3((G3+63)/64, Bb/64, Ll), 128>>>(pHp, pRp, pMH, bias_rec);
        for (int l = 0; l < Ll; l++) {
            if (l > 0) {
                // XP[t, :, l*3U:..] += H[l-1] @ skip_w[l-1]
                gemm_bf16_kernel<64,64,2,2><<<dim3((G3+63)/64, Bb/64), 128>>>(
                    pHp + (l-1) * KP_U, Ll * KP_U,
                    pSp + (size_t)(l-1) * KP_U * G3, G3,
                    pXP + (size_t)t * Bb * LDXP + l * G3, LDXP,
                    nullptr, G3, KP_U, 1);
            }
            gate_kernel<<<(Bb*KP_U + 255)/256, 256>>>(t, l);
        }
    }

    // 4. head: logits = Hp(as [B, L*U]) @ dense + bias, then softmax
    gemm_bf16_kernel<128,128,2,4><<<dim3(Vv/128, Bb/128), 256>>>(
        pHp, Ll*KP_U, pDp, Vv, out, Vv, dense_bias, Vv, KP_D, 0);
    softmax_kernel<<<Bb, 256>>>(out);
}